// round 17
// baseline (speedup 1.0000x reference)
#include <cuda_runtime.h>
#include <cuda_bf16.h>
#include <math_constants.h>
#include <cstdint>

// Gated global-add-pool: single fused kernel, per-warp cp.async smem rings.
// R17 = R11 (best measured, 24.8us) + occupancy experiment:
//   - s_acc aliases the ring smem (dead after drain+sync)  -> 40.2KB/CTA
//   - __launch_bounds__(256, 5) (regs capped ~51)          -> 5 CTAs/SM
// Everything else identical to R11 so the BW delta is attributable to
// occupancy (supply-side vs hard service-cap discrimination).
//
// Inputs (metadata order):
//   d_in[0] x       float32 [N, 256]
//   d_in[1] batch   int32 (jax x64 off) or int64 [N], sorted segment ids in [0,G)
//   d_in[2] gate_W  float32 [256, 1]
//   d_in[3] gate_b  float32 [1]
// Output: float32 [G, 256]
//
// Grid = SPLIT*G (SPLIT=2). Each warp owns rows lo+warp, lo+warp+8, ...
// through a PRIVATE 5-slot smem ring: 4 single-row cp.async groups in
// flight (wait_group<3> -> row i complete). Per-row: LDS.128 x2 ->
// dot -> 5-shfl butterfly -> exp -> 8 FMA. No barriers in the loop.
// End: cross-warp smem reduce (aliased) -> partial + weight-sum; last-CTA
// ticket combines SPLIT partials in fixed order (deterministic).
//
// No softmax max-subtraction: logits ~ N(0,1), exp safe in fp32; softmax is
// shift-invariant (measured rel_err ~3.7e-7 across R7-R16).

#define D_FEAT   256
#define NTHREADS 256
#define NWARPS   8
#define SPLIT    2
#define MAXB     4096              // >= SPLIT * n_segments
#define FULLMASK 0xffffffffu
#define K_PREF   4                 // cp.async groups in flight per warp
#define RING     5                 // K_PREF + 1 slots
#define ROW_B    1024              // bytes per row (256 fp32)

// dynamic smem: [rings (s_acc aliases start)][s_ps][s_range][s_last]
#define RINGS_B  (NWARPS * RING * ROW_B)                    // 40960
#define SMEM_B   (RINGS_B + NWARPS * 4 + 16)                // 41008

__device__ float g_partial[MAXB * D_FEAT];
__device__ float g_psum[MAXB];
__device__ int   g_ticket[MAXB / SPLIT];   // zero-init; self-resetting

__device__ __forceinline__ float dot4(float4 a, float4 w) {
    return a.x * w.x + a.y * w.y + a.z * w.z + a.w * w.w;
}

__device__ __forceinline__ void cp_async16(unsigned int smem_addr, const void* g) {
    asm volatile("cp.async.cg.shared.global [%0], [%1], 16;\n"
                 :: "r"(smem_addr), "l"(g));
}
__device__ __forceinline__ void cp_async_commit() {
    asm volatile("cp.async.commit_group;\n");
}
template <int N>
__device__ __forceinline__ void cp_async_wait() {
    asm volatile("cp.async.wait_group %0;\n" :: "n"(N));
}

// Warp-cooperative lower_bound (33-ary): ~4 rounds for n=1e5.
__device__ __forceinline__ int warp_lb_i32(const int* __restrict__ a, int n,
                                           int key, int lane) {
    int lo = 0, hi = n;
    while (hi - lo > 32) {
        int span = hi - lo;
        int pos = lo + (int)(((long long)span * (lane + 1)) / 33);
        unsigned m = __ballot_sync(FULLMASK, a[pos] < key);
        int c = __popc(m);
        int nlo = (c == 0)  ? lo : lo + (int)(((long long)span * c) / 33);
        int nhi = (c == 32) ? hi : lo + (int)(((long long)span * (c + 1)) / 33);
        lo = nlo; hi = nhi;
    }
    int idx = lo + lane;
    unsigned m = __ballot_sync(FULLMASK, (idx < hi) ? (a[idx] < key) : false);
    return lo + __popc(m);
}

__device__ __forceinline__ int warp_lb_i64(const long long* __restrict__ a,
                                           int n, long long key, int lane) {
    int lo = 0, hi = n;
    while (hi - lo > 32) {
        int span = hi - lo;
        int pos = lo + (int)(((long long)span * (lane + 1)) / 33);
        unsigned m = __ballot_sync(FULLMASK, a[pos] < key);
        int c = __popc(m);
        int nlo = (c == 0)  ? lo : lo + (int)(((long long)span * c) / 33);
        int nhi = (c == 32) ? hi : lo + (int)(((long long)span * (c + 1)) / 33);
        lo = nlo; hi = nhi;
    }
    int idx = lo + lane;
    unsigned m = __ballot_sync(FULLMASK, (idx < hi) ? (a[idx] < key) : false);
    return lo + __popc(m);
}

__global__ __launch_bounds__(NTHREADS, 5)
void gap_fused_kernel(const float* __restrict__ x,
                      const void* __restrict__ batch,
                      const float* __restrict__ gate_W,
                      const float* __restrict__ gate_b,
                      float* __restrict__ out,
                      int n_nodes) {
    extern __shared__ __align__(16) char dsmem[];
    float* s_ring  = (float*)dsmem;                  // NWARPS*RING*256 floats
    float* s_acc   = (float*)dsmem;                  // ALIASES rings (post-drain)
    float* s_ps    = (float*)(dsmem + RINGS_B);      // NWARPS
    int*   s_range = (int*)(s_ps + NWARPS);          // 2
    int*   s_last  = s_range + 2;                    // 1

    const int t    = threadIdx.x;
    const int lane = t & 31;
    const int warp = t >> 5;
    const int g    = blockIdx.x / SPLIT;
    const int h    = blockIdx.x % SPLIT;

    // warp 0 -> segment start, warp 1 -> segment end; dtype sniffed inline.
    if (warp < 2) {
        // probe in-bounds for either dtype: 8*(n/2) <= 4*n. int32 data packs
        // two sorted ids (hi word != 0) -> huge; genuine int64 id is small.
        const long long probe =
            ((const long long*)batch)[n_nodes >= 2 ? n_nodes / 2 - 1 : 0];
        const bool is64 = (probe >= 0 && probe < (1LL << 31));
        int r;
        if (is64)
            r = warp_lb_i64((const long long*)batch, n_nodes,
                            (long long)(g + warp), lane);
        else
            r = warp_lb_i32((const int*)batch, n_nodes, g + warp, lane);
        if (lane == 0) s_range[warp] = r;
    }
    __syncthreads();

    const int start = s_range[0];
    const int end   = s_range[1];
    const int len   = end - start;
    const int piece = (len + SPLIT - 1) / SPLIT;
    const int lo    = start + h * piece;
    const int hi    = min(end, lo + piece);
    const int count = max(0, hi - lo);

    const float bias = gate_b[0];
    // lane l owns columns [4l,4l+3] and [128+4l,128+4l+3]
    const float4 wlo = *(const float4*)(gate_W + 4 * lane);
    const float4 whi = *(const float4*)(gate_W + D_FEAT / 2 + 4 * lane);

    // this warp's rows: lo+warp, lo+warp+NWARPS, ...
    const int nrows_w = (count > warp) ? ((count - warp + NWARPS - 1) / NWARPS) : 0;
    const float* const myrow0 = x + (size_t)(lo + warp) * D_FEAT;
    float* const ring = s_ring + warp * RING * D_FEAT;
    const unsigned ringb =
        (unsigned)__cvta_generic_to_shared(ring) + (unsigned)(16 * lane);

    // prologue: commit exactly K_PREF single-row groups (empty past the end)
    #pragma unroll
    for (int k = 0; k < K_PREF; k++) {
        if (k < nrows_w) {
            const float* src = myrow0 + (size_t)(k * NWARPS) * D_FEAT;
            const unsigned dst = ringb + (unsigned)(k * ROW_B);
            cp_async16(dst,       src + 4 * lane);
            cp_async16(dst + 512, src + D_FEAT / 2 + 4 * lane);
        }
        cp_async_commit();
    }

    float4 acc_lo = make_float4(0.f, 0.f, 0.f, 0.f);
    float4 acc_hi = make_float4(0.f, 0.f, 0.f, 0.f);
    float  ssum   = 0.f;

    int slot = 0, pslot = K_PREF;   // pslot = (i + K_PREF) % RING
    for (int i = 0; i < nrows_w; i++) {
        cp_async_wait<K_PREF - 1>();   // group i (row i's data) completed

        const float4* sp = (const float4*)(ring + slot * D_FEAT);
        float4 a = sp[lane];
        float4 b = sp[lane + 32];

        // keep the pipe full: one commit per iteration (empty near the end)
        const int pf = i + K_PREF;
        if (pf < nrows_w) {
            const float* src = myrow0 + (size_t)(pf * NWARPS) * D_FEAT;
            const unsigned dst = ringb + (unsigned)(pslot * ROW_B);
            cp_async16(dst,       src + 4 * lane);
            cp_async16(dst + 512, src + D_FEAT / 2 + 4 * lane);
        }
        cp_async_commit();

        float p = dot4(a, wlo) + dot4(b, whi);
        #pragma unroll
        for (int off = 16; off; off >>= 1)
            p += __shfl_xor_sync(FULLMASK, p, off);
        const float e = __expf(p + bias);
        ssum += e;
        acc_lo.x = fmaf(e, a.x, acc_lo.x);
        acc_lo.y = fmaf(e, a.y, acc_lo.y);
        acc_lo.z = fmaf(e, a.z, acc_lo.z);
        acc_lo.w = fmaf(e, a.w, acc_lo.w);
        acc_hi.x = fmaf(e, b.x, acc_hi.x);
        acc_hi.y = fmaf(e, b.y, acc_hi.y);
        acc_hi.z = fmaf(e, b.z, acc_hi.z);
        acc_hi.w = fmaf(e, b.w, acc_hi.w);

        if (++slot == RING) slot = 0;
        if (++pslot == RING) pslot = 0;
    }
    cp_async_wait<0>();   // all groups drained (incl. empty ones)
    __syncthreads();      // ALL warps drained before s_acc aliases ring space

    // ---- cross-warp reduction (s_acc reuses ring smem) ----
    *(float4*)&s_acc[warp * D_FEAT + 4 * lane]              = acc_lo;
    *(float4*)&s_acc[warp * D_FEAT + D_FEAT / 2 + 4 * lane] = acc_hi;
    if (lane == 0) s_ps[warp] = ssum;   // ssum identical across lanes
    __syncthreads();

    float tot = 0.f;
    #pragma unroll
    for (int w = 0; w < NWARPS; w++)
        tot += s_acc[w * D_FEAT + t];
    g_partial[(size_t)blockIdx.x * D_FEAT + t] = tot;
    if (t == 0) {
        float s = 0.f;
        #pragma unroll
        for (int w = 0; w < NWARPS; w++)
            s += s_ps[w];
        g_psum[blockIdx.x] = s;
    }

    // ---- last-block combine (fixed order -> deterministic) ----
    __threadfence();
    if (t == 0) {
        int old = atomicAdd(&g_ticket[g], 1);
        *s_last = (old == SPLIT - 1);
    }
    __syncthreads();
    if (*s_last) {
        __threadfence();
        float v = 0.f;
        float s = 1e-16f;
        #pragma unroll
        for (int hh = 0; hh < SPLIT; hh++) {
            const int b = g * SPLIT + hh;
            v += g_partial[(size_t)b * D_FEAT + t];
            s += g_psum[b];
        }
        out[(size_t)g * D_FEAT + t] = v / s;
        if (t == 0) g_ticket[g] = 0;   // reset for next graph replay
    }
}

extern "C" void kernel_launch(void* const* d_in, const int* in_sizes, int n_in,
                              void* d_out, int out_size) {
    const float* x      = (const float*)d_in[0];
    const void*  batch  = d_in[1];
    const float* gate_W = (const float*)d_in[2];
    const float* gate_b = (const float*)d_in[3];
    float*       out    = (float*)d_out;

    const int n_nodes = in_sizes[1];
    const int n_seg   = out_size / D_FEAT;

    static int configured = 0;
    if (!configured) {
        cudaFuncSetAttribute(gap_fused_kernel,
                             cudaFuncAttributeMaxDynamicSharedMemorySize,
                             SMEM_B);
        configured = 1;
    }

    gap_fused_kernel<<<n_seg * SPLIT, NTHREADS, SMEM_B>>>(x, batch, gate_W,
                                                          gate_b, out, n_nodes);
}